// round 5
// baseline (speedup 1.0000x reference)
#include <cuda_runtime.h>
#include <cstdint>

#define K_TAGS 256
#define N_BATCH 64
#define T_SEQ 512

// ---- per-CTA shared memory layout (bytes) ----
#define OFF_A     0        // a[2][256] float = 2048 (full alpha vector, replicated)
#define OFF_MBAR  2048     // full[2] mbarriers (8 B each)
#define OFF_RED8  2064     // float2 red8[8] = 64
#define OFF_JTOT  2128     // joint total (pad to 16)
#define OFF_MASKR 2144     // 512 floats
#define OFF_TAGSR 4192     // 512 ints
#define SMEM_BYTES 6272

__device__ float g_Pexp[K_TAGS * K_TAGS];
__device__ float g_partial[N_BATCH];
__device__ int   g_done;

__device__ __forceinline__ unsigned long long ffma2(unsigned long long a,
                                                    unsigned long long b,
                                                    unsigned long long c) {
    unsigned long long d;
    asm("fma.rn.f32x2 %0, %1, %2, %3;" : "=l"(d) : "l"(a), "l"(b), "l"(c));
    return d;
}
__device__ __forceinline__ unsigned long long packf2(float lo, float hi) {
    unsigned long long r;
    asm("mov.b64 %0, {%1, %2};" : "=l"(r) : "f"(lo), "f"(hi));
    return r;
}
__device__ __forceinline__ float2 unpackf2(unsigned long long v) {
    float lo, hi;
    asm("mov.b64 {%0, %1}, %2;" : "=f"(lo), "=f"(hi) : "l"(v));
    return make_float2(lo, hi);
}
__device__ __forceinline__ uint32_t smem_u32(const void* p) {
    uint32_t r;
    asm("{ .reg .u64 t; cvta.to.shared.u64 t, %1; cvt.u32.u64 %0, t; }" : "=r"(r) : "l"(p));
    return r;
}
__device__ __forceinline__ uint32_t cluster_rank() {
    uint32_t r; asm("mov.u32 %0, %%cluster_ctarank;" : "=r"(r)); return r;
}
__device__ __forceinline__ uint32_t mapa32(uint32_t a, uint32_t rank) {
    uint32_t r; asm("mapa.shared::cluster.u32 %0, %1, %2;" : "=r"(r) : "r"(a), "r"(rank));
    return r;
}
__device__ __forceinline__ void mbar_init(uint32_t a, uint32_t cnt) {
    asm volatile("mbarrier.init.shared.b64 [%0], %1;" :: "r"(a), "r"(cnt) : "memory");
}
__device__ __forceinline__ void mbar_arrive_expect_tx(uint32_t a, uint32_t bytes) {
    asm volatile("mbarrier.arrive.expect_tx.shared.b64 _, [%0], %1;"
                 :: "r"(a), "r"(bytes) : "memory");
}
__device__ __forceinline__ void fence_proxy_async_sh() {
    asm volatile("fence.proxy.async.shared::cta;" ::: "memory");
}
// one bulk DSMEM copy, single complete_tx on the (cluster-mapped) dest mbarrier
__device__ __forceinline__ void bulk_s2s(uint32_t dst, uint32_t src,
                                         uint32_t bytes, uint32_t mbar) {
    asm volatile("cp.async.bulk.shared::cluster.shared::cta.mbarrier::complete_tx::bytes "
                 "[%0], [%1], %2, [%3];"
                 :: "r"(dst), "r"(src), "r"(bytes), "r"(mbar) : "memory");
}
__device__ __forceinline__ void mbar_wait_cluster(uint32_t a, uint32_t parity) {
    uint32_t done;
    asm volatile("{ .reg .pred p; mbarrier.try_wait.parity.acquire.cluster.shared::cta.b64 p, [%1], %2; selp.b32 %0, 1, 0, p; }"
                 : "=r"(done) : "r"(a), "r"(parity) : "memory");
    while (!done) {
        asm volatile("{ .reg .pred p; mbarrier.try_wait.parity.acquire.cluster.shared::cta.b64 p, [%1], %2, 0x989680; selp.b32 %0, 1, 0, p; }"
                     : "=r"(done) : "r"(a), "r"(parity) : "memory");
    }
}
#define CLUSTER_SYNC_() do { \
    asm volatile("barrier.cluster.arrive.aligned;" ::: "memory"); \
    asm volatile("barrier.cluster.wait.aligned;"   ::: "memory"); } while (0)

// ---- pre-kernel: P = exp(transitions), fp32 in gmem (once, chip-wide) ----
__global__ void pexp_kernel(const float* __restrict__ transitions)
{
    int idx = blockIdx.x * 256 + threadIdx.x;
    g_Pexp[idx] = __expf(transitions[idx]);
}

__global__ void __launch_bounds__(256, 1) __cluster_dims__(2, 1, 1)
crf_kernel(const float* __restrict__ logits,
           const int*   __restrict__ tags,
           const int*   __restrict__ mask,
           const float* __restrict__ transitions,
           float*       __restrict__ out)
{
    extern __shared__ char smem[];
    float*  a_sh    = (float*) (smem + OFF_A);
    float2* red8    = (float2*)(smem + OFF_RED8);
    float*  jtot_s  = (float*) (smem + OFF_JTOT);
    float*  mask_sh = (float*) (smem + OFF_MASKR);
    int*    tags_sh = (int*)   (smem + OFF_TAGSR);

    const int      b   = blockIdx.x >> 1;
    const uint32_t r   = cluster_rank();
    const int      tid = threadIdx.x;
    const int      jl  = tid >> 1;          // column pair index within CTA (0..127)
    const int      h   = tid & 1;           // i-half handled by this thread
    const int      jg  = (int)r * 128 + jl; // global column owned by this pair
    const unsigned base_bt = (unsigned)b * T_SEQ * K_TAGS;

    const uint32_t a_loc     = smem_u32(smem + OFF_A);
    const uint32_t mbar_loc  = smem_u32(smem + OFF_MBAR);
    const uint32_t a_peer    = mapa32(a_loc,    r ^ 1u);
    const uint32_t mbar_peer = mapa32(mbar_loc, r ^ 1u);
    const uint32_t half_off  = r * 512u;    // byte offset of our contiguous half

    // ---- init + arm both full barriers for their first phase ----
    if (tid == 0) {
        mbar_init(mbar_loc, 1);
        mbar_init(mbar_loc + 8, 1);
        mbar_arrive_expect_tx(mbar_loc,     512);
        mbar_arrive_expect_tx(mbar_loc + 8, 512);
    }

    // ---- stage tags / mask ----
    for (int t = tid; t < T_SEQ; t += 256) {
        tags_sh[t] = tags[b * T_SEQ + t];
        mask_sh[t] = (float)mask[b * T_SEQ + t];
    }

    // ---- P column (fp32) into registers: 128 terms = 64 f32x2 pairs ----
    unsigned long long preg[64];
    #pragma unroll
    for (int m = 0; m < 64; m++) {
        int i0 = h * 128 + 2 * m;
        preg[m] = packf2(g_Pexp[i0 * K_TAGS + jg], g_Pexp[(i0 + 1) * K_TAGS + jg]);
    }

    // ---- alpha0 local: a[0][j] = exp(logit0[j] - logit0[0]) for our columns ----
    const float L00 = logits[base_bt];
    if (h == 0) {
        float a0v = __expf(logits[base_bt + jg] - L00);
        a_sh[jg] = a0v;
    }
    float D = L00;    // used only by rank0 tid0

    __syncthreads();       // staging + barrier init + alpha0 local stores done
    CLUSTER_SYNC_();       // barriers armed cluster-wide before any bulk lands

    // ---- replicate alpha0 half to peer: ONE bulk, one complete_tx ----
    if (tid == 0) {
        fence_proxy_async_sh();
        bulk_s2s(a_peer + half_off, a_loc + half_off, 512, mbar_peer);
    }

    // ---- joint likelihood (rank 0 only; per-CTA barrier is safe here) ----
    if (r == 0) {
        float jloc = 0.f, msloc = 0.f;
        for (int t = tid; t < T_SEQ; t += 256) {
            float mt = mask_sh[t];
            int   tg = tags_sh[t];
            if (t < T_SEQ - 1)
                jloc += logits[base_bt + (unsigned)t * K_TAGS + tg] * mt;
            if (t >= 1)
                jloc += transitions[tags_sh[t - 1] * K_TAGS + tg] * mt;
            msloc += mt;
        }
        #pragma unroll
        for (int o = 16; o; o >>= 1) {
            jloc  += __shfl_xor_sync(0xffffffffu, jloc,  o);
            msloc += __shfl_xor_sync(0xffffffffu, msloc, o);
        }
        if ((tid & 31) == 0) red8[tid >> 5] = make_float2(jloc, msloc);
        __syncthreads();
        if (tid == 0) {
            float js = 0.f, ms = 0.f;
            #pragma unroll
            for (int w = 0; w < 8; w++) { js += red8[w].x; ms += red8[w].y; }
            int last_idx = (int)ms - 1;
            if (last_idx < 0) last_idx = 0;
            if (last_idx > T_SEQ - 1) last_idx = T_SEQ - 1;
            int ltag = tags_sh[last_idx];
            js += logits[base_bt + (unsigned)(T_SEQ - 1) * K_TAGS + ltag] * mask_sh[T_SEQ - 1];
            *jtot_s = js;
        }
    }

    // ---- main recursion: ONE __syncthreads + one mbar wait + one bulk per step ----
    uint32_t fpar0 = 0, fpar1 = 0;
    float lg_next = 0.f;
    if (h == 0) lg_next = logits[base_bt + K_TAGS + jg];   // t=1 prefetch

    int rb = 0;
    #pragma unroll 1
    for (int t = 1; t < T_SEQ; t++) {
        const int wb = rb ^ 1;
        const float lg   = lg_next;
        const float mval = mask_sh[t];
        if (h == 0 && t < T_SEQ - 1)
            lg_next = logits[base_bt + (unsigned)(t + 1) * K_TAGS + jg];

        // peer half of a[rb] arrived? (local half fenced by previous bottom barrier)
        const uint32_t mb = mbar_loc + (uint32_t)rb * 8u;
        mbar_wait_cluster(mb, rb ? fpar1 : fpar0);
        if (rb) fpar1 ^= 1u; else fpar0 ^= 1u;
        if (tid == 0) mbar_arrive_expect_tx(mb, 512);   // re-arm for next phase

        const float eL   = __expf(lg);                  // off-chain MUFU
        const float a0   = a_sh[rb * 256];
        const float inv0 = 1.0f / a0;                   // overlapped with matvec

        // half-column matvec: 64 packed FFMA2 on register-resident P
        const ulonglong2* ae = (const ulonglong2*)(a_sh + rb * 256 + h * 128);
        unsigned long long acc0 = 0ull, acc1 = 0ull, acc2 = 0ull, acc3 = 0ull;
        #pragma unroll
        for (int c = 0; c < 16; c++) {
            ulonglong2 v0 = ae[2 * c];
            ulonglong2 v1 = ae[2 * c + 1];
            acc0 = ffma2(v0.x, preg[4 * c],     acc0);
            acc1 = ffma2(v0.y, preg[4 * c + 1], acc1);
            acc2 = ffma2(v1.x, preg[4 * c + 2], acc2);
            acc3 = ffma2(v1.y, preg[4 * c + 3], acc3);
        }
        float2 u0 = unpackf2(acc0), u1 = unpackf2(acc1);
        float2 u2 = unpackf2(acc2), u3 = unpackf2(acc3);
        float part = ((u0.x + u0.y) + (u1.x + u1.y)) + ((u2.x + u2.y) + (u3.x + u3.y));

        const float tot = part + __shfl_xor_sync(0xffffffffu, part, 1);

        if (h == 0) {
            float g = (mval != 0.f) ? tot * eL * inv0 : a_sh[rb * 256 + jg];
            a_sh[wb * 256 + jg] = g;
            if (jg == 0 && mval != 0.f) D += __logf(a0);   // rank0 tid0 only
        }
        __syncthreads();   // all local stores of a[wb] done

        if (tid == 0) {    // ONE remote update: bulk 512B half -> peer, 1 complete_tx
            fence_proxy_async_sh();
            bulk_s2s(a_peer + (unsigned)wb * 1024u + half_off,
                     a_loc  + (unsigned)wb * 1024u + half_off,
                     512, mbar_peer + (uint32_t)wb * 8u);
        }
        rb = wb;
    }

    // ---- final: wait last buffer complete, then logsumexp ----
    mbar_wait_cluster(mbar_loc + (uint32_t)rb * 8u, rb ? fpar1 : fpar0);
    __syncthreads();

    if (r == 0) {
        float e = a_sh[rb * 256 + tid];
        #pragma unroll
        for (int o = 16; o; o >>= 1) e += __shfl_xor_sync(0xffffffffu, e, o);
        if ((tid & 31) == 0) red8[tid >> 5].x = e;
        __syncthreads();
        if (tid == 0) {
            float s = 0.f;
            #pragma unroll
            for (int w = 0; w < 8; w++) s += red8[w].x;
            float log_den = D + __logf(s);
            g_partial[b] = *jtot_s - log_den;
            __threadfence();
            int n = atomicAdd(&g_done, 1);
            if (n == N_BATCH - 1) {
                __threadfence();
                float acc = 0.f;
                #pragma unroll
                for (int bb = 0; bb < N_BATCH; bb++) acc += g_partial[bb];
                out[0] = acc;
                g_done = 0;
            }
        }
    }
    CLUSTER_SYNC_();
}

extern "C" void kernel_launch(void* const* d_in, const int* in_sizes, int n_in,
                              void* d_out, int out_size)
{
    (void)in_sizes; (void)n_in; (void)out_size;
    const float* logits      = (const float*)d_in[0];
    const int*   tags        = (const int*)  d_in[1];
    const int*   mask        = (const int*)  d_in[2];
    const float* transitions = (const float*)d_in[3];

    pexp_kernel<<<K_TAGS, 256>>>(transitions);
    crf_kernel<<<2 * N_BATCH, 256, SMEM_BYTES>>>(logits, tags, mask, transitions,
                                                 (float*)d_out);
}

// round 8
// speedup vs baseline: 1.4191x; 1.4191x over previous
#include <cuda_runtime.h>
#include <cstdint>

#define K_TAGS 256
#define N_BATCH 64
#define T_SEQ 512

// ---- per-CTA shared memory layout (bytes) ----
#define OFF_AOWN  0        // a_own[2][128] float: this CTA's own-column alphas
#define OFF_ABUF  1024     // a_buf[2][128] float: landing zone for peer alphas
#define OFF_PSUM  2048     // psum[128] float: early-group partial sums
#define OFF_MBAR  2560     // full[2] mbarriers (8 B each)
#define OFF_RED8  2576     // float2 red8[8] = 64
#define OFF_JTOT  2640
#define OFF_DSH   2644
#define OFF_MASKR 2648     // 512 floats
#define OFF_TAGSR 4696     // 512 ints
#define SMEM_BYTES 6784

__device__ float g_Pexp[K_TAGS * K_TAGS];
__device__ float g_partial[N_BATCH];
__device__ int   g_done;

__device__ __forceinline__ unsigned long long ffma2(unsigned long long a,
                                                    unsigned long long b,
                                                    unsigned long long c) {
    unsigned long long d;
    asm("fma.rn.f32x2 %0, %1, %2, %3;" : "=l"(d) : "l"(a), "l"(b), "l"(c));
    return d;
}
__device__ __forceinline__ unsigned long long packf2(float lo, float hi) {
    unsigned long long r;
    asm("mov.b64 %0, {%1, %2};" : "=l"(r) : "f"(lo), "f"(hi));
    return r;
}
__device__ __forceinline__ float2 unpackf2(unsigned long long v) {
    float lo, hi;
    asm("mov.b64 {%0, %1}, %2;" : "=f"(lo), "=f"(hi) : "l"(v));
    return make_float2(lo, hi);
}
__device__ __forceinline__ uint32_t smem_u32(const void* p) {
    uint32_t r;
    asm("{ .reg .u64 t; cvta.to.shared.u64 t, %1; cvt.u32.u64 %0, t; }" : "=r"(r) : "l"(p));
    return r;
}
__device__ __forceinline__ uint32_t cluster_rank() {
    uint32_t r; asm("mov.u32 %0, %%cluster_ctarank;" : "=r"(r)); return r;
}
__device__ __forceinline__ uint32_t mapa32(uint32_t a, uint32_t rank) {
    uint32_t r; asm("mapa.shared::cluster.u32 %0, %1, %2;" : "=r"(r) : "r"(a), "r"(rank));
    return r;
}
__device__ __forceinline__ void mbar_init(uint32_t a, uint32_t cnt) {
    asm volatile("mbarrier.init.shared.b64 [%0], %1;" :: "r"(a), "r"(cnt) : "memory");
}
__device__ __forceinline__ void mbar_arrive_expect_tx(uint32_t a, uint32_t bytes) {
    asm volatile("mbarrier.arrive.expect_tx.shared.b64 _, [%0], %1;"
                 :: "r"(a), "r"(bytes) : "memory");
}
__device__ __forceinline__ void st_async_b64(uint32_t dst, unsigned long long val,
                                             uint32_t mbar) {
    asm volatile("st.async.shared::cluster.mbarrier::complete_tx::bytes.b64 [%0], %1, [%2];"
                 :: "r"(dst), "l"(val), "r"(mbar) : "memory");
}
__device__ __forceinline__ void mbar_wait_cluster(uint32_t a, uint32_t parity) {
    uint32_t done;
    asm volatile("{ .reg .pred p; mbarrier.try_wait.parity.acquire.cluster.shared::cta.b64 p, [%1], %2; selp.b32 %0, 1, 0, p; }"
                 : "=r"(done) : "r"(a), "r"(parity) : "memory");
    while (!done) {
        asm volatile("{ .reg .pred p; mbarrier.try_wait.parity.acquire.cluster.shared::cta.b64 p, [%1], %2, 0x989680; selp.b32 %0, 1, 0, p; }"
                     : "=r"(done) : "r"(a), "r"(parity) : "memory");
    }
}
#define CLUSTER_SYNC_() do { \
    asm volatile("barrier.cluster.arrive.aligned;" ::: "memory"); \
    asm volatile("barrier.cluster.wait.aligned;"   ::: "memory"); } while (0)

// ---- pre-kernel: P = exp(transitions), fp32 in gmem (once, chip-wide) ----
__global__ void pexp_kernel(const float* __restrict__ transitions)
{
    int idx = blockIdx.x * 256 + threadIdx.x;
    g_Pexp[idx] = __expf(transitions[idx]);
}

__global__ void __launch_bounds__(256, 1) __cluster_dims__(2, 1, 1)
crf_kernel(const float* __restrict__ logits,
           const int*   __restrict__ tags,
           const int*   __restrict__ mask,
           const float* __restrict__ transitions,
           float*       __restrict__ out)
{
    extern __shared__ char smem[];
    float*  a_own   = (float*) (smem + OFF_AOWN);
    float*  a_buf   = (float*) (smem + OFF_ABUF);
    float*  psum    = (float*) (smem + OFF_PSUM);
    float2* red8    = (float2*)(smem + OFF_RED8);
    float*  jtot_s  = (float*) (smem + OFF_JTOT);
    float*  D_sh    = (float*) (smem + OFF_DSH);
    float*  mask_sh = (float*) (smem + OFF_MASKR);
    int*    tags_sh = (int*)   (smem + OFF_TAGSR);

    const int      b   = blockIdx.x >> 1;
    const uint32_t r   = cluster_rank();
    const int      tid = threadIdx.x;
    const int      jl  = tid & 127;          // output column (local index)
    const int      grp = tid >> 7;           // 0 = early (own-i half), 1 = late (peer-i half)
    const int      jg  = (int)r * 128 + jl;  // global output column
    const unsigned base_bt = (unsigned)b * T_SEQ * K_TAGS;

    const uint32_t abuf_loc  = smem_u32(smem + OFF_ABUF);
    const uint32_t mbar_loc  = smem_u32(smem + OFF_MBAR);
    const uint32_t abuf_peer = mapa32(abuf_loc, r ^ 1u);
    const uint32_t mbar_peer = mapa32(mbar_loc, r ^ 1u);

    if (tid == 0) {
        mbar_init(mbar_loc, 1);
        mbar_init(mbar_loc + 8, 1);
        mbar_arrive_expect_tx(mbar_loc,     512);
        mbar_arrive_expect_tx(mbar_loc + 8, 512);
    }

    // ---- stage tags / mask ----
    for (int t = tid; t < T_SEQ; t += 256) {
        tags_sh[t] = tags[b * T_SEQ + t];
        mask_sh[t] = (float)mask[b * T_SEQ + t];
    }

    // ---- P block into registers: rows = availability half, col = jg ----
    // early (grp 0): i in OWN rank's half; late (grp 1): i in PEER rank's half
    const int ibase = (grp == 0) ? (int)r * 128 : (int)(r ^ 1u) * 128;
    unsigned long long preg[64];
    #pragma unroll
    for (int m = 0; m < 64; m++) {
        int i0 = ibase + 2 * m;
        preg[m] = packf2(g_Pexp[i0 * K_TAGS + jg], g_Pexp[(i0 + 1) * K_TAGS + jg]);
    }

    // ---- alpha0 for own columns (late group computes & stores locally) ----
    const float L00 = logits[base_bt];
    float a0v = 0.f;
    if (grp == 1) {
        a0v = __expf(logits[base_bt + jg] - L00);
        a_own[jl] = a0v;             // buffer 0 (read at t=1)
    }
    float D = L00;                   // tracked by rank0 tid128
    __syncthreads();                 // staging + alpha0 local + mbar init done

    // ---- joint likelihood (rank 0 only; per-CTA barriers legal) ----
    if (r == 0) {
        float jloc = 0.f, msloc = 0.f;
        for (int t = tid; t < T_SEQ; t += 256) {
            float mt = mask_sh[t];
            int   tg = tags_sh[t];
            if (t < T_SEQ - 1)
                jloc += logits[base_bt + (unsigned)t * K_TAGS + tg] * mt;
            if (t >= 1)
                jloc += transitions[tags_sh[t - 1] * K_TAGS + tg] * mt;
            msloc += mt;
        }
        #pragma unroll
        for (int o = 16; o; o >>= 1) {
            jloc  += __shfl_xor_sync(0xffffffffu, jloc,  o);
            msloc += __shfl_xor_sync(0xffffffffu, msloc, o);
        }
        if ((tid & 31) == 0) red8[tid >> 5] = make_float2(jloc, msloc);
        __syncthreads();
        if (tid == 0) {
            float js = 0.f, ms = 0.f;
            #pragma unroll
            for (int w = 0; w < 8; w++) { js += red8[w].x; ms += red8[w].y; }
            int last_idx = (int)ms - 1;
            if (last_idx < 0) last_idx = 0;
            if (last_idx > T_SEQ - 1) last_idx = T_SEQ - 1;
            int ltag = tags_sh[last_idx];
            js += logits[base_bt + (unsigned)(T_SEQ - 1) * K_TAGS + ltag] * mask_sh[T_SEQ - 1];
            *jtot_s = js;
        }
    }

    CLUSTER_SYNC_();   // barriers armed cluster-wide before any st.async

    // ---- send alpha0 half to peer's a_buf[0] (paired b64: 64 tx-updates) ----
    if (grp == 1) {
        float gp = __shfl_down_sync(0xffffffffu, a0v, 1);
        if (!(jl & 1))
            st_async_b64(abuf_peer + (unsigned)jl * 4u, packf2(a0v, gp), mbar_peer);
    }

    uint32_t fpar0 = 0, fpar1 = 0;

    #pragma unroll 1
    for (int t = 1; t < T_SEQ; t++) {
        const int rb = (t - 1) & 1, wb = t & 1;
        const float mval = mask_sh[t];

        float part, eL = 0.f, inv0 = 0.f, a0 = 0.f;
        if (grp == 0) {
            // ---- early: own-half partial, no wait (local data) ----
            const ulonglong2* ae = (const ulonglong2*)(a_own + rb * 128);
            unsigned long long acc0 = 0ull, acc1 = 0ull, acc2 = 0ull, acc3 = 0ull;
            #pragma unroll
            for (int c = 0; c < 16; c++) {
                ulonglong2 v0 = ae[2 * c];
                ulonglong2 v1 = ae[2 * c + 1];
                acc0 = ffma2(v0.x, preg[4 * c],     acc0);
                acc1 = ffma2(v0.y, preg[4 * c + 1], acc1);
                acc2 = ffma2(v1.x, preg[4 * c + 2], acc2);
                acc3 = ffma2(v1.y, preg[4 * c + 3], acc3);
            }
            float2 u0 = unpackf2(acc0), u1 = unpackf2(acc1);
            float2 u2 = unpackf2(acc2), u3 = unpackf2(acc3);
            part = ((u0.x + u0.y) + (u1.x + u1.y)) + ((u2.x + u2.y) + (u3.x + u3.y));
            psum[jl] = part;
        } else {
            // ---- late: wait for peer half, then peer-half partial ----
            const float lg = logits[base_bt + (unsigned)t * K_TAGS + jg];

            const uint32_t mb = mbar_loc + (uint32_t)rb * 8u;
            mbar_wait_cluster(mb, rb ? fpar1 : fpar0);
            if (rb) fpar1 ^= 1u; else fpar0 ^= 1u;
            if (tid == 128) mbar_arrive_expect_tx(mb, 512);   // re-arm

            // global a[0]: rank0 owns col 0 locally; rank1 receives it in a_buf
            a0   = (r == 0) ? a_own[rb * 128] : a_buf[rb * 128];
            inv0 = 1.0f / a0;
            eL   = __expf(lg);

            const ulonglong2* ae = (const ulonglong2*)(a_buf + rb * 128);
            unsigned long long acc0 = 0ull, acc1 = 0ull, acc2 = 0ull, acc3 = 0ull;
            #pragma unroll
            for (int c = 0; c < 16; c++) {
                ulonglong2 v0 = ae[2 * c];
                ulonglong2 v1 = ae[2 * c + 1];
                acc0 = ffma2(v0.x, preg[4 * c],     acc0);
                acc1 = ffma2(v0.y, preg[4 * c + 1], acc1);
                acc2 = ffma2(v1.x, preg[4 * c + 2], acc2);
                acc3 = ffma2(v1.y, preg[4 * c + 3], acc3);
            }
            float2 u0 = unpackf2(acc0), u1 = unpackf2(acc1);
            float2 u2 = unpackf2(acc2), u3 = unpackf2(acc3);
            part = ((u0.x + u0.y) + (u1.x + u1.y)) + ((u2.x + u2.y) + (u3.x + u3.y));
        }

        __syncthreads();   // B: psum visible; early also fenced from touching next buf

        if (grp == 1) {
            float tot   = part + psum[jl];
            float aprev = a_own[rb * 128 + jl];
            float g     = (mval != 0.f) ? tot * eL * inv0 : aprev;
            a_own[wb * 128 + jl] = g;

            float gp = __shfl_down_sync(0xffffffffu, g, 1);
            if (!(jl & 1))
                st_async_b64(abuf_peer + (unsigned)(wb * 128 + jl) * 4u,
                             packf2(g, gp), mbar_peer + (uint32_t)wb * 8u);

            if (r == 0 && jl == 0 && mval != 0.f) D += __logf(a0);
        }

        __syncthreads();   // C: a_own[wb] visible to early for next step
    }

    // ---- final: last buffer is wb=1; wait peer half, reduce on rank 0 ----
    if (grp == 1) {
        mbar_wait_cluster(mbar_loc + 8u, fpar1);
        if (r == 0 && tid == 128) *D_sh = D;
    }
    __syncthreads();

    if (r == 0) {
        float e = (tid < 128) ? a_own[128 + tid] : a_buf[128 + (tid - 128)];
        #pragma unroll
        for (int o = 16; o; o >>= 1) e += __shfl_xor_sync(0xffffffffu, e, o);
        if ((tid & 31) == 0) red8[tid >> 5].x = e;
        __syncthreads();
        if (tid == 0) {
            float s = 0.f;
            #pragma unroll
            for (int w = 0; w < 8; w++) s += red8[w].x;
            float log_den = *D_sh + __logf(s);
            g_partial[b] = *jtot_s - log_den;
            __threadfence();
            int n = atomicAdd(&g_done, 1);
            if (n == N_BATCH - 1) {
                __threadfence();
                float acc = 0.f;
                #pragma unroll
                for (int bb = 0; bb < N_BATCH; bb++) acc += g_partial[bb];
                out[0] = acc;
                g_done = 0;
            }
        }
    }
    CLUSTER_SYNC_();
}

extern "C" void kernel_launch(void* const* d_in, const int* in_sizes, int n_in,
                              void* d_out, int out_size)
{
    (void)in_sizes; (void)n_in; (void)out_size;
    const float* logits      = (const float*)d_in[0];
    const int*   tags        = (const int*)  d_in[1];
    const int*   mask        = (const int*)  d_in[2];
    const float* transitions = (const float*)d_in[3];

    pexp_kernel<<<K_TAGS, 256>>>(transitions);
    crf_kernel<<<2 * N_BATCH, 256, SMEM_BYTES>>>(logits, tags, mask, transitions,
                                                 (float*)d_out);
}

// round 10
// speedup vs baseline: 1.5321x; 1.0796x over previous
#include <cuda_runtime.h>
#include <cuda_bf16.h>
#include <cstdint>

#define K_TAGS 256
#define N_BATCH 64
#define T_SEQ 512

__device__ unsigned g_Pbf[K_TAGS * (K_TAGS / 2)];   // [j][m]: bf16x2 pair (i=2m,2m+1), col j
__device__ float    g_partial[N_BATCH];
__device__ int      g_done;

__device__ __forceinline__ unsigned bffma2(unsigned a, unsigned b, unsigned c) {
    unsigned d;
    asm("fma.rn.bf16x2 %0, %1, %2, %3;" : "=r"(d) : "r"(a), "r"(b), "r"(c));
    return d;
}
__device__ __forceinline__ unsigned long long addf2(unsigned long long a,
                                                    unsigned long long b) {
    unsigned long long d;
    asm("add.rn.f32x2 %0, %1, %2;" : "=l"(d) : "l"(a), "l"(b));
    return d;
}
__device__ __forceinline__ unsigned long long packf2(float lo, float hi) {
    unsigned long long r;
    asm("mov.b64 %0, {%1, %2};" : "=l"(r) : "f"(lo), "f"(hi));
    return r;
}
__device__ __forceinline__ float2 unpackf2(unsigned long long v) {
    float lo, hi;
    asm("mov.b64 {%0, %1}, %2;" : "=f"(lo), "=f"(hi) : "l"(v));
    return make_float2(lo, hi);
}
// bf16x2 -> two f32 (lo = bits<<16, hi = bits & 0xffff0000)
__device__ __forceinline__ unsigned long long bf2f2(unsigned u) {
    return packf2(__uint_as_float(u << 16), __uint_as_float(u & 0xffff0000u));
}

// ---- pre-kernel: P[j][m] = pack(bf16(exp(T[2m][j])), bf16(exp(T[2m+1][j]))) ----
__global__ void pexp_kernel(const float* __restrict__ transitions)
{
    int j = blockIdx.x;      // 256 blocks
    int m = threadIdx.x;     // 128 threads
    float e0 = __expf(transitions[(2 * m)     * K_TAGS + j]);
    float e1 = __expf(transitions[(2 * m + 1) * K_TAGS + j]);
    unsigned lo = (__float_as_uint(e0) + 0x8000u) >> 16;   // rn-ish to bf16
    unsigned hi = (__float_as_uint(e1) + 0x8000u) >> 16;
    // use precise cvt instead:
    __nv_bfloat16 b0 = __float2bfloat16(e0);
    __nv_bfloat16 b1 = __float2bfloat16(e1);
    unsigned u0 = (unsigned)*reinterpret_cast<unsigned short*>(&b0);
    unsigned u1 = (unsigned)*reinterpret_cast<unsigned short*>(&b1);
    (void)lo; (void)hi;
    g_Pbf[j * 128 + m] = u0 | (u1 << 16);
}

__global__ void __launch_bounds__(256, 1)
crf_kernel(const float* __restrict__ logits,
           const int*   __restrict__ tags,
           const int*   __restrict__ mask,
           const float* __restrict__ transitions,
           float*       __restrict__ out)
{
    __shared__ __align__(16) unsigned short a_sh[2][K_TAGS];   // bf16 alphas
    __shared__ float  a0f[2];
    __shared__ float2 red8[8];
    __shared__ float  jtot_s;
    __shared__ float  mask_sh[T_SEQ];
    __shared__ int    tags_sh[T_SEQ];

    const int b   = blockIdx.x;
    const int j   = threadIdx.x;
    const unsigned base_bt = (unsigned)b * T_SEQ * K_TAGS;

    // ---- stage tags / mask ----
    for (int t = j; t < T_SEQ; t += 256) {
        tags_sh[t] = tags[b * T_SEQ + t];
        mask_sh[t] = (float)mask[b * T_SEQ + t];
    }

    // ---- P column into registers: 128 bf16x2 (32 x LDG.128) ----
    unsigned preg[128];
    #pragma unroll
    for (int m = 0; m < 128; m++) preg[m] = g_Pbf[j * 128 + m];

    // ---- alpha0 (scaled-exp form, normalizer = col 0) ----
    const float L00 = logits[base_bt];
    float aval = __expf(logits[base_bt + j] - L00);
    a_sh[0][j] = __bfloat16_as_ushort(__float2bfloat16(aval));
    if (j == 0) a0f[0] = aval;          // = 1.0
    float D = L00;
    __syncthreads();

    // ---- joint likelihood ----
    {
        float jloc = 0.f, msloc = 0.f;
        for (int t = j; t < T_SEQ; t += 256) {
            float mt = mask_sh[t];
            int   tg = tags_sh[t];
            if (t < T_SEQ - 1)
                jloc += logits[base_bt + (unsigned)t * K_TAGS + tg] * mt;
            if (t >= 1)
                jloc += transitions[tags_sh[t - 1] * K_TAGS + tg] * mt;
            msloc += mt;
        }
        #pragma unroll
        for (int o = 16; o; o >>= 1) {
            jloc  += __shfl_xor_sync(0xffffffffu, jloc,  o);
            msloc += __shfl_xor_sync(0xffffffffu, msloc, o);
        }
        if ((j & 31) == 0) red8[j >> 5] = make_float2(jloc, msloc);
        __syncthreads();
        if (j == 0) {
            float js = 0.f, ms = 0.f;
            #pragma unroll
            for (int w = 0; w < 8; w++) { js += red8[w].x; ms += red8[w].y; }
            int last_idx = (int)ms - 1;
            if (last_idx < 0) last_idx = 0;
            if (last_idx > T_SEQ - 1) last_idx = T_SEQ - 1;
            int ltag = tags_sh[last_idx];
            js += logits[base_bt + (unsigned)(T_SEQ - 1) * K_TAGS + ltag] * mask_sh[T_SEQ - 1];
            jtot_s = js;
        }
    }
    __syncthreads();

    // ---- main recursion: ONE __syncthreads per step, all-smem ----
    float lg_cur = logits[base_bt + K_TAGS + j];   // t=1
    #pragma unroll 1
    for (int t = 1; t < T_SEQ; t++) {
        const int rb = (t - 1) & 1, wb = t & 1;
        const float mval = mask_sh[t];

        float lg_next = 0.f;
        if (t < T_SEQ - 1) lg_next = logits[base_bt + (unsigned)(t + 1) * K_TAGS + j];

        const float eL   = __expf(lg_cur);
        const float a0   = a0f[rb];
        const float inv0 = 1.0f / a0;

        // dot: 128 HFMA2 over broadcast bf16 alphas, 8 rotating accumulators
        const uint4* av = (const uint4*)a_sh[rb];
        unsigned ac0 = 0u, ac1 = 0u, ac2 = 0u, ac3 = 0u;
        unsigned ac4 = 0u, ac5 = 0u, ac6 = 0u, ac7 = 0u;
        #pragma unroll
        for (int c = 0; c < 16; c++) {
            uint4 v0 = av[2 * c];
            uint4 v1 = av[2 * c + 1];
            ac0 = bffma2(v0.x, preg[8 * c + 0], ac0);
            ac1 = bffma2(v0.y, preg[8 * c + 1], ac1);
            ac2 = bffma2(v0.z, preg[8 * c + 2], ac2);
            ac3 = bffma2(v0.w, preg[8 * c + 3], ac3);
            ac4 = bffma2(v1.x, preg[8 * c + 4], ac4);
            ac5 = bffma2(v1.y, preg[8 * c + 5], ac5);
            ac6 = bffma2(v1.z, preg[8 * c + 6], ac6);
            ac7 = bffma2(v1.w, preg[8 * c + 7], ac7);
        }
        // combine in fp32 (f32x2 tree)
        unsigned long long s0 = addf2(bf2f2(ac0), bf2f2(ac1));
        unsigned long long s1 = addf2(bf2f2(ac2), bf2f2(ac3));
        unsigned long long s2 = addf2(bf2f2(ac4), bf2f2(ac5));
        unsigned long long s3 = addf2(bf2f2(ac6), bf2f2(ac7));
        unsigned long long s4 = addf2(addf2(s0, s1), addf2(s2, s3));
        float2 uf = unpackf2(s4);
        const float tot = uf.x + uf.y;

        const float g = (mval != 0.f) ? tot * eL * inv0 : aval;
        aval = g;
        a_sh[wb][j] = __bfloat16_as_ushort(__float2bfloat16(g));
        if (j == 0) {
            a0f[wb] = g;
            if (mval != 0.f) D += __logf(a0);
        }
        lg_cur = lg_next;
        __syncthreads();
    }

    // ---- final logsumexp from fp32 per-thread aval ----
    {
        float e = aval;
        #pragma unroll
        for (int o = 16; o; o >>= 1) e += __shfl_xor_sync(0xffffffffu, e, o);
        if ((j & 31) == 0) red8[j >> 5].x = e;
        if (j == 0) red8[0].y = D;          // col-0 thread's D
        __syncthreads();
        if (j == 0) {
            float s = 0.f;
            #pragma unroll
            for (int w = 0; w < 8; w++) s += red8[w].x;
            float log_den = red8[0].y + __logf(s);
            g_partial[b] = jtot_s - log_den;
            __threadfence();
            int n = atomicAdd(&g_done, 1);
            if (n == N_BATCH - 1) {          // last CTA finalizes, fixed order
                __threadfence();
                float acc = 0.f;
                #pragma unroll
                for (int bb = 0; bb < N_BATCH; bb++) acc += g_partial[bb];
                out[0] = acc;
                g_done = 0;                  // reset for next graph replay
            }
        }
    }
}

extern "C" void kernel_launch(void* const* d_in, const int* in_sizes, int n_in,
                              void* d_out, int out_size)
{
    (void)in_sizes; (void)n_in; (void)out_size;
    const float* logits      = (const float*)d_in[0];
    const int*   tags        = (const int*)  d_in[1];
    const int*   mask        = (const int*)  d_in[2];
    const float* transitions = (const float*)d_in[3];

    pexp_kernel<<<K_TAGS, K_TAGS / 2>>>(transitions);
    crf_kernel<<<N_BATCH, 256>>>(logits, tags, mask, transitions, (float*)d_out);
}

// round 13
// speedup vs baseline: 1.7274x; 1.1274x over previous
#include <cuda_runtime.h>
#include <cuda_bf16.h>
#include <cstdint>

#define K_TAGS 256
#define N_BATCH 64
#define T_SEQ 512
#define MID    255            // forward produces alpha_255; backward produces beta_255

__device__ unsigned g_Pcol[K_TAGS * (K_TAGS / 2)];  // fwd: [j][m] = bf16x2(exp T[2m][j], exp T[2m+1][j])
__device__ unsigned g_Prow[K_TAGS * (K_TAGS / 2)];  // bwd: [i][m] = bf16x2(exp T[i][2m], exp T[i][2m+1])
__device__ float    g_af[N_BATCH * K_TAGS];         // forward stored alpha (fp32)
__device__ float    g_Df[N_BATCH];
__device__ float    g_jt[N_BATCH];
__device__ int      g_flag[N_BATCH];
__device__ float    g_partial[N_BATCH];
__device__ int      g_done;

__device__ __forceinline__ unsigned bffma2(unsigned a, unsigned b, unsigned c) {
    unsigned d;
    asm("fma.rn.bf16x2 %0, %1, %2, %3;" : "=r"(d) : "r"(a), "r"(b), "r"(c));
    return d;
}
__device__ __forceinline__ unsigned long long addf2(unsigned long long a,
                                                    unsigned long long b) {
    unsigned long long d;
    asm("add.rn.f32x2 %0, %1, %2;" : "=l"(d) : "l"(a), "l"(b));
    return d;
}
__device__ __forceinline__ unsigned long long packf2(float lo, float hi) {
    unsigned long long r;
    asm("mov.b64 %0, {%1, %2};" : "=l"(r) : "f"(lo), "f"(hi));
    return r;
}
__device__ __forceinline__ float2 unpackf2(unsigned long long v) {
    float lo, hi;
    asm("mov.b64 {%0, %1}, %2;" : "=f"(lo), "=f"(hi) : "l"(v));
    return make_float2(lo, hi);
}
__device__ __forceinline__ unsigned long long bf2f2(unsigned u) {
    return packf2(__uint_as_float(u << 16), __uint_as_float(u & 0xffff0000u));
}
__device__ __forceinline__ unsigned packbf(float a, float b) {
    __nv_bfloat162 h = __floats2bfloat162_rn(a, b);
    return *reinterpret_cast<unsigned*>(&h);
}
__device__ __forceinline__ unsigned short f2bfu(float a) {
    __nv_bfloat16 h = __float2bfloat16(a);
    return *reinterpret_cast<unsigned short*>(&h);
}

// ---- pre-kernel: both bf16x2 layouts of exp(transitions) ----
__global__ void pexp_kernel(const float* __restrict__ transitions)
{
    int j = blockIdx.x;      // 256
    int m = threadIdx.x;     // 128
    float c0 = __expf(transitions[(2 * m)     * K_TAGS + j]);
    float c1 = __expf(transitions[(2 * m + 1) * K_TAGS + j]);
    g_Pcol[j * 128 + m] = packbf(c0, c1);
    float r0 = __expf(transitions[j * K_TAGS + 2 * m]);
    float r1 = __expf(transitions[j * K_TAGS + 2 * m + 1]);
    g_Prow[j * 128 + m] = packbf(r0, r1);
}

// dot: 128 HFMA2 over broadcast bf16 vector in smem, combine in f32x2
__device__ __forceinline__ float dot256(const unsigned short* vec,
                                        const unsigned* preg)
{
    const uint4* av = (const uint4*)vec;
    unsigned ac0 = 0u, ac1 = 0u, ac2 = 0u, ac3 = 0u;
    unsigned ac4 = 0u, ac5 = 0u, ac6 = 0u, ac7 = 0u;
    #pragma unroll
    for (int c = 0; c < 16; c++) {
        uint4 v0 = av[2 * c];
        uint4 v1 = av[2 * c + 1];
        ac0 = bffma2(v0.x, preg[8 * c + 0], ac0);
        ac1 = bffma2(v0.y, preg[8 * c + 1], ac1);
        ac2 = bffma2(v0.z, preg[8 * c + 2], ac2);
        ac3 = bffma2(v0.w, preg[8 * c + 3], ac3);
        ac4 = bffma2(v1.x, preg[8 * c + 4], ac4);
        ac5 = bffma2(v1.y, preg[8 * c + 5], ac5);
        ac6 = bffma2(v1.z, preg[8 * c + 6], ac6);
        ac7 = bffma2(v1.w, preg[8 * c + 7], ac7);
    }
    unsigned long long s0 = addf2(bf2f2(ac0), bf2f2(ac1));
    unsigned long long s1 = addf2(bf2f2(ac2), bf2f2(ac3));
    unsigned long long s2 = addf2(bf2f2(ac4), bf2f2(ac5));
    unsigned long long s3 = addf2(bf2f2(ac6), bf2f2(ac7));
    unsigned long long s4 = addf2(addf2(s0, s1), addf2(s2, s3));
    float2 uf = unpackf2(s4);
    return uf.x + uf.y;
}

__global__ void __launch_bounds__(256, 1)
crf_kernel(const float* __restrict__ logits,
           const int*   __restrict__ tags,
           const int*   __restrict__ mask,
           const float* __restrict__ transitions,
           float*       __restrict__ out)
{
    __shared__ __align__(16) unsigned short a_sh[2][K_TAGS];
    __shared__ float  n0f[2];           // fp32 normalizer (element 0)
    __shared__ float2 red8[8];
    __shared__ float  jtot_s;
    __shared__ float  mask_sh[T_SEQ];
    __shared__ int    tags_sh[T_SEQ];

    const int b    = blockIdx.x & (N_BATCH - 1);
    const int role = blockIdx.x >> 6;        // 0 = forward, 1 = backward
    const int j    = threadIdx.x;
    const unsigned base_bt = (unsigned)b * T_SEQ * K_TAGS;

    // ---- stage mask (both roles), tags (fwd only) ----
    for (int t = j; t < T_SEQ; t += 256) {
        mask_sh[t] = (float)mask[b * T_SEQ + t];
        if (role == 0) tags_sh[t] = tags[b * T_SEQ + t];
    }

    // ---- P block into registers (column for fwd, row for bwd) ----
    const unsigned* psrc = (role == 0) ? g_Pcol : g_Prow;
    unsigned preg[128];
    #pragma unroll
    for (int m = 0; m < 128; m++) preg[m] = psrc[j * 128 + m];

    if (role == 0) {
        // ================= FORWARD: alpha_0 .. alpha_255 =================
        const float L00 = logits[base_bt];
        float aval = __expf(logits[base_bt + j] - L00);
        a_sh[0][j] = f2bfu(aval);
        if (j == 0) n0f[0] = aval;
        float D = L00;
        __syncthreads();

        // joint likelihood
        {
            float jloc = 0.f, msloc = 0.f;
            for (int t = j; t < T_SEQ; t += 256) {
                float mt = mask_sh[t];
                int   tg = tags_sh[t];
                if (t < T_SEQ - 1)
                    jloc += logits[base_bt + (unsigned)t * K_TAGS + tg] * mt;
                if (t >= 1)
                    jloc += transitions[tags_sh[t - 1] * K_TAGS + tg] * mt;
                msloc += mt;
            }
            #pragma unroll
            for (int o = 16; o; o >>= 1) {
                jloc  += __shfl_xor_sync(0xffffffffu, jloc,  o);
                msloc += __shfl_xor_sync(0xffffffffu, msloc, o);
            }
            if ((j & 31) == 0) red8[j >> 5] = make_float2(jloc, msloc);
            __syncthreads();
            if (j == 0) {
                float js = 0.f, ms = 0.f;
                #pragma unroll
                for (int w = 0; w < 8; w++) { js += red8[w].x; ms += red8[w].y; }
                int last_idx = (int)ms - 1;
                if (last_idx < 0) last_idx = 0;
                if (last_idx > T_SEQ - 1) last_idx = T_SEQ - 1;
                int ltag = tags_sh[last_idx];
                js += logits[base_bt + (unsigned)(T_SEQ - 1) * K_TAGS + ltag] * mask_sh[T_SEQ - 1];
                jtot_s = js;
            }
        }
        __syncthreads();

        float lg_cur = logits[base_bt + K_TAGS + j];   // t=1
        #pragma unroll 1
        for (int t = 1; t <= MID; t++) {
            const int rb = (t - 1) & 1, wb = t & 1;
            const float mval = mask_sh[t];
            float lg_next = 0.f;
            if (t < MID) lg_next = logits[base_bt + (unsigned)(t + 1) * K_TAGS + j];

            const float eL   = __expf(lg_cur);
            const float a0   = n0f[rb];
            const float inv0 = 1.0f / a0;

            const float tot = dot256(a_sh[rb], preg);

            const float g = (mval != 0.f) ? tot * eL * inv0 : aval;
            aval = g;
            a_sh[wb][j] = f2bfu(g);
            if (j == 0) {
                n0f[wb] = g;
                if (mval != 0.f) D += __logf(a0);
            }
            lg_cur = lg_next;
            __syncthreads();
        }

        // handoff: stored alpha (fp32), D_f, joint -> gmem, then flag
        g_af[b * K_TAGS + j] = aval;
        if (j == 0) { g_Df[b] = D; g_jt[b] = jtot_s; }
        __syncthreads();
        __threadfence();
        if (j == 0) atomicExch(&g_flag[b], 1);
    } else {
        // ================= BACKWARD: beta_511 -> beta_255 =================
        float bval = 1.0f;
        if (j == 0) n0f[0] = 1.0f;     // normalizer for first iteration (k=0 reads n0f[0])
        float D = 0.f;

        float lg_cur = logits[base_bt + (unsigned)(T_SEQ - 1) * K_TAGS + j];
        __syncthreads();

        #pragma unroll 1
        for (int t = T_SEQ - 1; t > MID; t--) {
            const int k  = (T_SEQ - 1) - t;       // 0..255
            const int cb = k & 1, nb = cb ^ 1;
            const float mval = mask_sh[t];
            float lg_next = 0.f;
            if (t > MID + 1) lg_next = logits[base_bt + (unsigned)(t - 1) * K_TAGS + j];

            const float eL = __expf(lg_cur);
            a_sh[cb][j] = f2bfu(eL * bval);       // c = eL ⊙ beta
            __syncthreads();                       // c + n0f[cb] visible

            const float b0   = n0f[cb];
            const float inv0 = 1.0f / b0;

            const float tot = dot256(a_sh[cb], preg);   // row i: P[i,:]·c

            const float g = (mval != 0.f) ? tot * inv0 : bval;
            bval = g;
            if (j == 0) {
                n0f[nb] = g;                       // normalizer for next iteration
                if (mval != 0.f) D += __logf(b0);
            }
            lg_cur = lg_next;
        }

        // ---- combine: wait for forward, dot, emit ----
        if (j == 0) {
            while (atomicAdd(&g_flag[b], 0) == 0) { }
            __threadfence();
        }
        __syncthreads();

        float e = g_af[b * K_TAGS + j] * bval;
        #pragma unroll
        for (int o = 16; o; o >>= 1) e += __shfl_xor_sync(0xffffffffu, e, o);
        if ((j & 31) == 0) red8[j >> 5].x = e;
        __syncthreads();
        if (j == 0) {
            float s = 0.f;
            #pragma unroll
            for (int w = 0; w < 8; w++) s += red8[w].x;
            float log_den = __logf(s) + g_Df[b] + D;
            g_partial[b] = g_jt[b] - log_den;
            g_flag[b] = 0;                         // reset for next replay
            __threadfence();
            int n = atomicAdd(&g_done, 1);
            if (n == N_BATCH - 1) {                // last backward CTA finalizes
                __threadfence();
                float acc = 0.f;
                #pragma unroll
                for (int bb = 0; bb < N_BATCH; bb++) acc += g_partial[bb];
                out[0] = acc;
                g_done = 0;
            }
        }
    }
}

extern "C" void kernel_launch(void* const* d_in, const int* in_sizes, int n_in,
                              void* d_out, int out_size)
{
    (void)in_sizes; (void)n_in; (void)out_size;
    const float* logits      = (const float*)d_in[0];
    const int*   tags        = (const int*)  d_in[1];
    const int*   mask        = (const int*)  d_in[2];
    const float* transitions = (const float*)d_in[3];

    pexp_kernel<<<K_TAGS, K_TAGS / 2>>>(transitions);
    crf_kernel<<<2 * N_BATCH, 256>>>(logits, tags, mask, transitions, (float*)d_out);
}

// round 14
// speedup vs baseline: 1.9208x; 1.1120x over previous
#include <cuda_runtime.h>
#include <cuda_bf16.h>
#include <cstdint>

#define K_TAGS 256
#define N_BATCH 64
#define T_SEQ 512
#define MID    255
#define NTHR   512

__device__ unsigned g_Pcol[K_TAGS * (K_TAGS / 2)];  // fwd: [j][m] = bf16x2(exp T[2m][j], exp T[2m+1][j])
__device__ unsigned g_Prow[K_TAGS * (K_TAGS / 2)];  // bwd: [i][m] = bf16x2(exp T[i][2m], exp T[i][2m+1])
__device__ float    g_af[N_BATCH * K_TAGS];
__device__ float    g_Df[N_BATCH];
__device__ float    g_jt[N_BATCH];
__device__ int      g_flag[N_BATCH];
__device__ float    g_partial[N_BATCH];
__device__ int      g_done;

__device__ __forceinline__ unsigned bffma2(unsigned a, unsigned b, unsigned c) {
    unsigned d;
    asm("fma.rn.bf16x2 %0, %1, %2, %3;" : "=r"(d) : "r"(a), "r"(b), "r"(c));
    return d;
}
__device__ __forceinline__ unsigned long long addf2(unsigned long long a,
                                                    unsigned long long b) {
    unsigned long long d;
    asm("add.rn.f32x2 %0, %1, %2;" : "=l"(d) : "l"(a), "l"(b));
    return d;
}
__device__ __forceinline__ unsigned long long packf2(float lo, float hi) {
    unsigned long long r;
    asm("mov.b64 %0, {%1, %2};" : "=l"(r) : "f"(lo), "f"(hi));
    return r;
}
__device__ __forceinline__ float2 unpackf2(unsigned long long v) {
    float lo, hi;
    asm("mov.b64 {%0, %1}, %2;" : "=f"(lo), "=f"(hi) : "l"(v));
    return make_float2(lo, hi);
}
__device__ __forceinline__ unsigned long long bf2f2(unsigned u) {
    return packf2(__uint_as_float(u << 16), __uint_as_float(u & 0xffff0000u));
}
__device__ __forceinline__ unsigned packbf(float a, float b) {
    __nv_bfloat162 h = __floats2bfloat162_rn(a, b);
    return *reinterpret_cast<unsigned*>(&h);
}
__device__ __forceinline__ unsigned short f2bfu(float a) {
    __nv_bfloat16 h = __float2bfloat16(a);
    return *reinterpret_cast<unsigned short*>(&h);
}

__global__ void pexp_kernel(const float* __restrict__ transitions)
{
    int j = blockIdx.x;      // 256
    int m = threadIdx.x;     // 128
    float c0 = __expf(transitions[(2 * m)     * K_TAGS + j]);
    float c1 = __expf(transitions[(2 * m + 1) * K_TAGS + j]);
    g_Pcol[j * 128 + m] = packbf(c0, c1);
    float r0 = __expf(transitions[j * K_TAGS + 2 * m]);
    float r1 = __expf(transitions[j * K_TAGS + 2 * m + 1]);
    g_Prow[j * 128 + m] = packbf(r0, r1);
}

// half-dot: 64 HFMA2 over one 128-element half of the broadcast bf16 vector
__device__ __forceinline__ float dot128(const unsigned short* vec_half,
                                        const unsigned* preg)
{
    const uint4* av = (const uint4*)vec_half;     // 16 uint4 = 128 bf16
    unsigned ac0 = 0u, ac1 = 0u, ac2 = 0u, ac3 = 0u;
    unsigned ac4 = 0u, ac5 = 0u, ac6 = 0u, ac7 = 0u;
    #pragma unroll
    for (int c = 0; c < 8; c++) {
        uint4 v0 = av[2 * c];
        uint4 v1 = av[2 * c + 1];
        ac0 = bffma2(v0.x, preg[8 * c + 0], ac0);
        ac1 = bffma2(v0.y, preg[8 * c + 1], ac1);
        ac2 = bffma2(v0.z, preg[8 * c + 2], ac2);
        ac3 = bffma2(v0.w, preg[8 * c + 3], ac3);
        ac4 = bffma2(v1.x, preg[8 * c + 4], ac4);
        ac5 = bffma2(v1.y, preg[8 * c + 5], ac5);
        ac6 = bffma2(v1.z, preg[8 * c + 6], ac6);
        ac7 = bffma2(v1.w, preg[8 * c + 7], ac7);
    }
    unsigned long long s0 = addf2(bf2f2(ac0), bf2f2(ac1));
    unsigned long long s1 = addf2(bf2f2(ac2), bf2f2(ac3));
    unsigned long long s2 = addf2(bf2f2(ac4), bf2f2(ac5));
    unsigned long long s3 = addf2(bf2f2(ac6), bf2f2(ac7));
    unsigned long long s4 = addf2(addf2(s0, s1), addf2(s2, s3));
    float2 uf = unpackf2(s4);
    return uf.x + uf.y;
}

__global__ void __launch_bounds__(NTHR, 1)
crf_kernel(const float* __restrict__ logits,
           const int*   __restrict__ tags,
           const int*   __restrict__ mask,
           const float* __restrict__ transitions,
           float*       __restrict__ out)
{
    __shared__ __align__(16) unsigned short a_sh[2][K_TAGS];
    __shared__ float  n0f[2];
    __shared__ float2 red16[16];
    __shared__ float  jtot_s;
    __shared__ float  mask_sh[T_SEQ];
    __shared__ int    tags_sh[T_SEQ];

    const int b    = blockIdx.x & (N_BATCH - 1);
    const int role = blockIdx.x >> 6;        // 0 = forward, 1 = backward
    const int tid  = threadIdx.x;
    const int j    = tid >> 1;               // column
    const int h    = tid & 1;                // i-half
    const unsigned base_bt = (unsigned)b * T_SEQ * K_TAGS;

    // ---- stage mask (both), tags (fwd only): one element per thread ----
    {
        int t = tid;
        mask_sh[t] = (float)mask[b * T_SEQ + t];
        if (role == 0) tags_sh[t] = tags[b * T_SEQ + t];
    }

    // ---- P half-block into registers: 64 bf16x2 ----
    const unsigned* psrc = (role == 0) ? g_Pcol : g_Prow;
    unsigned preg[64];
    #pragma unroll
    for (int m = 0; m < 64; m++) preg[m] = psrc[j * 128 + h * 64 + m];

    if (role == 0) {
        // ================= FORWARD: alpha_0 .. alpha_255 =================
        const float L00 = logits[base_bt];
        float aval = __expf(logits[base_bt + j] - L00);
        if (h == 0) a_sh[0][j] = f2bfu(aval);
        if (tid == 0) n0f[0] = aval;
        float D = L00;
        __syncthreads();

        // joint likelihood (one t per thread)
        {
            int   t  = tid;
            float mt = mask_sh[t];
            int   tg = tags_sh[t];
            float jloc = 0.f;
            if (t < T_SEQ - 1)
                jloc += logits[base_bt + (unsigned)t * K_TAGS + tg] * mt;
            if (t >= 1)
                jloc += transitions[tags_sh[t - 1] * K_TAGS + tg] * mt;
            float msloc = mt;
            #pragma unroll
            for (int o = 16; o; o >>= 1) {
                jloc  += __shfl_xor_sync(0xffffffffu, jloc,  o);
                msloc += __shfl_xor_sync(0xffffffffu, msloc, o);
            }
            if ((tid & 31) == 0) red16[tid >> 5] = make_float2(jloc, msloc);
            __syncthreads();
            if (tid == 0) {
                float js = 0.f, ms = 0.f;
                #pragma unroll
                for (int w = 0; w < 16; w++) { js += red16[w].x; ms += red16[w].y; }
                int last_idx = (int)ms - 1;
                if (last_idx < 0) last_idx = 0;
                if (last_idx > T_SEQ - 1) last_idx = T_SEQ - 1;
                int ltag = tags_sh[last_idx];
                js += logits[base_bt + (unsigned)(T_SEQ - 1) * K_TAGS + ltag] * mask_sh[T_SEQ - 1];
                jtot_s = js;
            }
        }
        __syncthreads();

        float lg_cur = logits[base_bt + K_TAGS + j];   // t=1
        #pragma unroll 1
        for (int t = 1; t <= MID; t++) {
            const int rb = (t - 1) & 1, wb = t & 1;
            const float mval = mask_sh[t];
            float lg_next = 0.f;
            if (t < MID) lg_next = logits[base_bt + (unsigned)(t + 1) * K_TAGS + j];

            const float eL   = __expf(lg_cur);
            const float a0   = n0f[rb];
            const float inv0 = 1.0f / a0;

            float part = dot128(a_sh[rb] + h * 128, preg);
            float tot  = part + __shfl_xor_sync(0xffffffffu, part, 1);

            const float g = (mval != 0.f) ? tot * eL * inv0 : aval;
            aval = g;
            if (h == 0) a_sh[wb][j] = f2bfu(g);
            if (tid == 0) {
                n0f[wb] = g;
                if (mval != 0.f) D += __logf(a0);
            }
            lg_cur = lg_next;
            __syncthreads();
        }

        // handoff
        if (h == 0) g_af[b * K_TAGS + j] = aval;
        if (tid == 0) { g_Df[b] = D; g_jt[b] = jtot_s; }
        __syncthreads();
        __threadfence();
        if (tid == 0) atomicExch(&g_flag[b], 1);
    } else {
        // ================= BACKWARD: beta_511 -> beta_255 =================
        float bval = 1.0f;
        if (tid == 0) n0f[0] = 1.0f;
        float D = 0.f;

        float lg_cur = logits[base_bt + (unsigned)(T_SEQ - 1) * K_TAGS + j];
        __syncthreads();

        #pragma unroll 1
        for (int t = T_SEQ - 1; t > MID; t--) {
            const int k  = (T_SEQ - 1) - t;
            const int cb = k & 1, nb = cb ^ 1;
            const float mval = mask_sh[t];
            float lg_next = 0.f;
            if (t > MID + 1) lg_next = logits[base_bt + (unsigned)(t - 1) * K_TAGS + j];

            const float eL = __expf(lg_cur);
            if (h == 0) a_sh[cb][j] = f2bfu(eL * bval);   // c = eL ⊙ beta
            __syncthreads();

            const float b0   = n0f[cb];
            const float inv0 = 1.0f / b0;

            float part = dot128(a_sh[cb] + h * 128, preg);
            float tot  = part + __shfl_xor_sync(0xffffffffu, part, 1);

            const float g = (mval != 0.f) ? tot * inv0 : bval;
            bval = g;
            if (tid == 0) {
                n0f[nb] = g;
                if (mval != 0.f) D += __logf(b0);
            }
            lg_cur = lg_next;
        }

        // ---- combine with forward ----
        if (tid == 0) {
            while (atomicAdd(&g_flag[b], 0) == 0) { }
            __threadfence();
        }
        __syncthreads();

        float e = (h == 0) ? g_af[b * K_TAGS + j] * bval : 0.f;
        #pragma unroll
        for (int o = 16; o; o >>= 1) e += __shfl_xor_sync(0xffffffffu, e, o);
        if ((tid & 31) == 0) red16[tid >> 5].x = e;
        __syncthreads();
        if (tid == 0) {
            float s = 0.f;
            #pragma unroll
            for (int w = 0; w < 16; w++) s += red16[w].x;
            float log_den = __logf(s) + g_Df[b] + D;
            g_partial[b] = g_jt[b] - log_den;
            g_flag[b] = 0;
            __threadfence();
            int n = atomicAdd(&g_done, 1);
            if (n == N_BATCH - 1) {
                __threadfence();
                float acc = 0.f;
                #pragma unroll
                for (int bb = 0; bb < N_BATCH; bb++) acc += g_partial[bb];
                out[0] = acc;
                g_done = 0;
            }
        }
    }
}

extern "C" void kernel_launch(void* const* d_in, const int* in_sizes, int n_in,
                              void* d_out, int out_size)
{
    (void)in_sizes; (void)n_in; (void)out_size;
    const float* logits      = (const float*)d_in[0];
    const int*   tags        = (const int*)  d_in[1];
    const int*   mask        = (const int*)  d_in[2];
    const float* transitions = (const float*)d_in[3];

    pexp_kernel<<<K_TAGS, K_TAGS / 2>>>(transitions);
    crf_kernel<<<2 * N_BATCH, NTHR>>>(logits, tags, mask, transitions, (float*)d_out);
}

// round 15
// speedup vs baseline: 2.0896x; 1.0878x over previous
#include <cuda_runtime.h>
#include <cuda_bf16.h>
#include <cstdint>

#define K_TAGS 256
#define N_BATCH 64
#define T_SEQ 512
#define MID    255
#define NTHR   512

__device__ unsigned g_Pcol[K_TAGS * (K_TAGS / 2)];  // fwd: [j][m] = bf16x2(exp T[2m][j], exp T[2m+1][j])
__device__ unsigned g_Prow[K_TAGS * (K_TAGS / 2)];  // bwd: [i][m] = bf16x2(exp T[i][2m], exp T[i][2m+1])
__device__ float    g_af[N_BATCH * K_TAGS];
__device__ float    g_Df[N_BATCH];
__device__ float    g_jt[N_BATCH];
__device__ int      g_flag[N_BATCH];
__device__ float    g_partial[N_BATCH];
__device__ int      g_done;

__device__ __forceinline__ unsigned bffma2(unsigned a, unsigned b, unsigned c) {
    unsigned d;
    asm("fma.rn.bf16x2 %0, %1, %2, %3;" : "=r"(d) : "r"(a), "r"(b), "r"(c));
    return d;
}
__device__ __forceinline__ unsigned bfadd2(unsigned a, unsigned b) {
    unsigned d;
    asm("add.rn.bf16x2 %0, %1, %2;" : "=r"(d) : "r"(a), "r"(b));
    return d;
}
__device__ __forceinline__ unsigned packbf(float a, float b) {
    __nv_bfloat162 h = __floats2bfloat162_rn(a, b);
    return *reinterpret_cast<unsigned*>(&h);
}
__device__ __forceinline__ unsigned short f2bfu(float a) {
    __nv_bfloat16 h = __float2bfloat16(a);
    return *reinterpret_cast<unsigned short*>(&h);
}

__global__ void pexp_kernel(const float* __restrict__ transitions)
{
    int j = blockIdx.x;      // 256
    int m = threadIdx.x;     // 128
    float c0 = __expf(transitions[(2 * m)     * K_TAGS + j]);
    float c1 = __expf(transitions[(2 * m + 1) * K_TAGS + j]);
    g_Pcol[j * 128 + m] = packbf(c0, c1);
    float r0 = __expf(transitions[j * K_TAGS + 2 * m]);
    float r1 = __expf(transitions[j * K_TAGS + 2 * m + 1]);
    g_Prow[j * 128 + m] = packbf(r0, r1);
}

// half-dot: 64 HFMA2 over one 128-element half; combine via HADD2 tree
__device__ __forceinline__ float dot128(const unsigned short* vec_half,
                                        const unsigned* preg)
{
    const uint4* av = (const uint4*)vec_half;     // 16 uint4 = 128 bf16
    unsigned ac0 = 0u, ac1 = 0u, ac2 = 0u, ac3 = 0u;
    unsigned ac4 = 0u, ac5 = 0u, ac6 = 0u, ac7 = 0u;
    #pragma unroll
    for (int c = 0; c < 8; c++) {
        uint4 v0 = av[2 * c];
        uint4 v1 = av[2 * c + 1];
        ac0 = bffma2(v0.x, preg[8 * c + 0], ac0);
        ac1 = bffma2(v0.y, preg[8 * c + 1], ac1);
        ac2 = bffma2(v0.z, preg[8 * c + 2], ac2);
        ac3 = bffma2(v0.w, preg[8 * c + 3], ac3);
        ac4 = bffma2(v1.x, preg[8 * c + 4], ac4);
        ac5 = bffma2(v1.y, preg[8 * c + 5], ac5);
        ac6 = bffma2(v1.z, preg[8 * c + 6], ac6);
        ac7 = bffma2(v1.w, preg[8 * c + 7], ac7);
    }
    unsigned s0 = bfadd2(ac0, ac1);
    unsigned s1 = bfadd2(ac2, ac3);
    unsigned s2 = bfadd2(ac4, ac5);
    unsigned s3 = bfadd2(ac6, ac7);
    unsigned s  = bfadd2(bfadd2(s0, s1), bfadd2(s2, s3));
    float lo = __uint_as_float(s << 16);
    float hi = __uint_as_float(s & 0xffff0000u);
    return lo + hi;
}

__global__ void __launch_bounds__(NTHR, 1)
crf_kernel(const float* __restrict__ logits,
           const int*   __restrict__ tags,
           const int*   __restrict__ mask,
           const float* __restrict__ transitions,
           float*       __restrict__ out)
{
    __shared__ __align__(16) unsigned short a_sh[2][K_TAGS];
    __shared__ float  n0[T_SEQ / 2 + 2];     // normalizer ring (258 floats)
    __shared__ float2 red16[16];
    __shared__ float  jtot_s;
    __shared__ float  mask_sh[T_SEQ];
    __shared__ int    tags_sh[T_SEQ];

    const int b    = blockIdx.x & (N_BATCH - 1);
    const int role = blockIdx.x >> 6;        // 0 = forward, 1 = backward
    const int tid  = threadIdx.x;
    const int j    = tid >> 1;               // column / row
    const int h    = tid & 1;                // half of contraction
    const unsigned base_bt = (unsigned)b * T_SEQ * K_TAGS;

    // ---- stage mask (both), tags (fwd only): one element per thread ----
    {
        int t = tid;
        mask_sh[t] = (float)mask[b * T_SEQ + t];
        if (role == 0) tags_sh[t] = tags[b * T_SEQ + t];
    }

    // ---- P half-block into registers: 64 bf16x2 ----
    const unsigned* psrc = (role == 0) ? g_Pcol : g_Prow;
    unsigned preg[64];
    #pragma unroll
    for (int m = 0; m < 64; m++) preg[m] = psrc[j * 128 + h * 64 + m];

    if (role == 0) {
        // ================= FORWARD: alpha_0 .. alpha_255 =================
        const float L00 = logits[base_bt];
        float aval = __expf(logits[base_bt + j] - L00);
        if (h == 0) a_sh[0][j] = f2bfu(aval);
        if (tid == 0) n0[0] = aval;          // = 1.0
        __syncthreads();

        // joint likelihood (one t per thread)
        {
            int   t  = tid;
            float mt = mask_sh[t];
            int   tg = tags_sh[t];
            float jloc = 0.f;
            if (t < T_SEQ - 1)
                jloc += logits[base_bt + (unsigned)t * K_TAGS + tg] * mt;
            if (t >= 1)
                jloc += transitions[tags_sh[t - 1] * K_TAGS + tg] * mt;
            float msloc = mt;
            #pragma unroll
            for (int o = 16; o; o >>= 1) {
                jloc  += __shfl_xor_sync(0xffffffffu, jloc,  o);
                msloc += __shfl_xor_sync(0xffffffffu, msloc, o);
            }
            if ((tid & 31) == 0) red16[tid >> 5] = make_float2(jloc, msloc);
            __syncthreads();
            if (tid == 0) {
                float js = 0.f, ms = 0.f;
                #pragma unroll
                for (int w = 0; w < 16; w++) { js += red16[w].x; ms += red16[w].y; }
                int last_idx = (int)ms - 1;
                if (last_idx < 0) last_idx = 0;
                if (last_idx > T_SEQ - 1) last_idx = T_SEQ - 1;
                int ltag = tags_sh[last_idx];
                js += logits[base_bt + (unsigned)(T_SEQ - 1) * K_TAGS + ltag] * mask_sh[T_SEQ - 1];
                jtot_s = js;
            }
        }
        __syncthreads();

        float lg_cur = logits[base_bt + K_TAGS + j];   // t=1
        #pragma unroll 2
        for (int t = 1; t <= MID; t++) {
            const int rb = (t - 1) & 1, wb = t & 1;
            const float mval = mask_sh[t];
            // branchless prefetch (clamped)
            const int tn = (t < MID) ? t + 1 : MID;
            const float lg_next = logits[base_bt + (unsigned)tn * K_TAGS + j];

            const float eL   = __expf(lg_cur);
            const float a0   = n0[t - 1];
            const float inv0 = 1.0f / a0;

            float part = dot128(a_sh[rb] + h * 128, preg);
            float tot  = part + __shfl_xor_sync(0xffffffffu, part, 1);

            const float g = (mval != 0.f) ? tot * eL * inv0 : aval;
            aval = g;
            if (h == 0) a_sh[wb][j] = f2bfu(g);
            if (tid == 0) n0[t] = g;           // ring write; no logf here
            lg_cur = lg_next;
            __syncthreads();
        }

        // ---- parallel D: D = L00 + sum_{t=1..255} mask_t * log(n0[t-1]) ----
        {
            float dl = 0.f;
            if (tid == 0)                    dl = L00;
            else if (tid <= MID)             dl = mask_sh[tid] * __logf(n0[tid - 1]);
            #pragma unroll
            for (int o = 16; o; o >>= 1) dl += __shfl_xor_sync(0xffffffffu, dl, o);
            if ((tid & 31) == 0) red16[tid >> 5].x = dl;
            __syncthreads();

            if (h == 0) g_af[b * K_TAGS + j] = aval;
            if (tid == 0) {
                float D = 0.f;
                #pragma unroll
                for (int w = 0; w < 16; w++) D += red16[w].x;
                g_Df[b] = D;
                g_jt[b] = jtot_s;
            }
            __syncthreads();
            __threadfence();
            if (tid == 0) atomicExch(&g_flag[b], 1);
        }
    } else {
        // ================= BACKWARD: beta_511 -> beta_255 =================
        float bval = 1.0f;
        if (tid == 0) n0[0] = 1.0f;          // nb ring: nb[k] = normalizer for step k

        float lg_cur = logits[base_bt + (unsigned)(T_SEQ - 1) * K_TAGS + j];
        __syncthreads();

        #pragma unroll 2
        for (int k = 0; k < 256; k++) {
            const int t  = (T_SEQ - 1) - k;
            const int cb = k & 1;
            const float mval = mask_sh[t];
            const int tn = (t > MID + 1) ? t - 1 : MID + 1;
            const float lg_next = logits[base_bt + (unsigned)tn * K_TAGS + j];

            const float eL = __expf(lg_cur);
            if (h == 0) a_sh[cb][j] = f2bfu(eL * bval);   // c = eL ⊙ beta
            __syncthreads();

            const float b0   = n0[k];
            const float inv0 = 1.0f / b0;

            float part = dot128(a_sh[cb] + h * 128, preg);
            float tot  = part + __shfl_xor_sync(0xffffffffu, part, 1);

            const float g = (mval != 0.f) ? tot * inv0 : bval;
            bval = g;
            if (tid == 0) n0[k + 1] = g;       // ring write; no logf here
            lg_cur = lg_next;
        }
        __syncthreads();                       // n0 ring complete

        // ---- parallel D_b = sum_{k=0..255} mask_{511-k} * log(nb[k]) ----
        float dl = 0.f;
        if (tid < 256) dl = mask_sh[(T_SEQ - 1) - tid] * __logf(n0[tid]);
        #pragma unroll
        for (int o = 16; o; o >>= 1) dl += __shfl_xor_sync(0xffffffffu, dl, o);
        if ((tid & 31) == 0) red16[tid >> 5].y = dl;

        // ---- wait for forward, combine ----
        if (tid == 0) {
            while (atomicAdd(&g_flag[b], 0) == 0) { }
            __threadfence();
        }
        __syncthreads();

        float e = (h == 0) ? g_af[b * K_TAGS + j] * bval : 0.f;
        #pragma unroll
        for (int o = 16; o; o >>= 1) e += __shfl_xor_sync(0xffffffffu, e, o);
        if ((tid & 31) == 0) red16[tid >> 5].x = e;
        __syncthreads();
        if (tid == 0) {
            float s = 0.f, Db = 0.f;
            #pragma unroll
            for (int w = 0; w < 16; w++) { s += red16[w].x; Db += red16[w].y; }
            float log_den = __logf(s) + g_Df[b] + Db;
            g_partial[b] = g_jt[b] - log_den;
            g_flag[b] = 0;
            __threadfence();
            int n = atomicAdd(&g_done, 1);
            if (n == N_BATCH - 1) {
                __threadfence();
                float acc = 0.f;
                #pragma unroll
                for (int bb = 0; bb < N_BATCH; bb++) acc += g_partial[bb];
                out[0] = acc;
                g_done = 0;
            }
        }
    }
}

extern "C" void kernel_launch(void* const* d_in, const int* in_sizes, int n_in,
                              void* d_out, int out_size)
{
    (void)in_sizes; (void)n_in; (void)out_size;
    const float* logits      = (const float*)d_in[0];
    const int*   tags        = (const int*)  d_in[1];
    const int*   mask        = (const int*)  d_in[2];
    const float* transitions = (const float*)d_in[3];

    pexp_kernel<<<K_TAGS, K_TAGS / 2>>>(transitions);
    crf_kernel<<<2 * N_BATCH, NTHR>>>(logits, tags, mask, transitions, (float*)d_out);
}

// round 17
// speedup vs baseline: 2.1653x; 1.0362x over previous
#include <cuda_runtime.h>
#include <cuda_fp16.h>
#include <cstdint>

#define K_TAGS 256
#define N_BATCH 64
#define T_SEQ 512
#define MID    255
#define NTHR   512
#define ASCALE   0.00390625f   // 1/256 storage scale for fp16 alphas
#define ASCALE_R 256.0f

__device__ unsigned g_Pcol[K_TAGS * (K_TAGS / 2)];  // fwd: [j][m] = f16x2(exp T[2m][j], exp T[2m+1][j])
__device__ unsigned g_Prow[K_TAGS * (K_TAGS / 2)];  // bwd: [i][m] = f16x2(exp T[i][2m], exp T[i][2m+1])
__device__ float    g_af[N_BATCH * K_TAGS];
__device__ float    g_Df[N_BATCH];
__device__ int      g_flag[N_BATCH];
__device__ float    g_partial[N_BATCH];
__device__ int      g_done;

__device__ __forceinline__ unsigned hfma2(unsigned a, unsigned b, unsigned c) {
    unsigned d;
    asm("fma.rn.f16x2 %0, %1, %2, %3;" : "=r"(d) : "r"(a), "r"(b), "r"(c));
    return d;
}
__device__ __forceinline__ unsigned hadd2(unsigned a, unsigned b) {
    unsigned d;
    asm("add.rn.f16x2 %0, %1, %2;" : "=r"(d) : "r"(a), "r"(b));
    return d;
}
__device__ __forceinline__ unsigned packh2(float a, float b) {
    __half2 h = __floats2half2_rn(a, b);
    return *reinterpret_cast<unsigned*>(&h);
}
__device__ __forceinline__ unsigned short f2hu(float a) {
    __half h = __float2half(a);
    return *reinterpret_cast<unsigned short*>(&h);
}

__global__ void pexp_kernel(const float* __restrict__ transitions)
{
    int j = blockIdx.x;      // 256
    int m = threadIdx.x;     // 128
    float c0 = __expf(transitions[(2 * m)     * K_TAGS + j]);
    float c1 = __expf(transitions[(2 * m + 1) * K_TAGS + j]);
    g_Pcol[j * 128 + m] = packh2(c0, c1);
    float r0 = __expf(transitions[j * K_TAGS + 2 * m]);
    float r1 = __expf(transitions[j * K_TAGS + 2 * m + 1]);
    g_Prow[j * 128 + m] = packh2(r0, r1);
}

// half-dot: 64 fp16x2 HFMA2 over one 128-element half; fp16 combine tree
__device__ __forceinline__ float dot128(const unsigned short* vec_half,
                                        const unsigned* preg)
{
    const uint4* av = (const uint4*)vec_half;     // 16 uint4 = 128 fp16
    unsigned ac0 = 0u, ac1 = 0u, ac2 = 0u, ac3 = 0u;
    unsigned ac4 = 0u, ac5 = 0u, ac6 = 0u, ac7 = 0u;
    #pragma unroll
    for (int c = 0; c < 8; c++) {
        uint4 v0 = av[2 * c];
        uint4 v1 = av[2 * c + 1];
        ac0 = hfma2(v0.x, preg[8 * c + 0], ac0);
        ac1 = hfma2(v0.y, preg[8 * c + 1], ac1);
        ac2 = hfma2(v0.z, preg[8 * c + 2], ac2);
        ac3 = hfma2(v0.w, preg[8 * c + 3], ac3);
        ac4 = hfma2(v1.x, preg[8 * c + 4], ac4);
        ac5 = hfma2(v1.y, preg[8 * c + 5], ac5);
        ac6 = hfma2(v1.z, preg[8 * c + 6], ac6);
        ac7 = hfma2(v1.w, preg[8 * c + 7], ac7);
    }
    unsigned s0 = hadd2(ac0, ac1);
    unsigned s1 = hadd2(ac2, ac3);
    unsigned s2 = hadd2(ac4, ac5);
    unsigned s3 = hadd2(ac6, ac7);
    unsigned s  = hadd2(hadd2(s0, s1), hadd2(s2, s3));
    float2 f = __half22float2(*reinterpret_cast<__half2*>(&s));
    return f.x + f.y;
}

__global__ void __launch_bounds__(NTHR, 1)
crf_kernel(const float* __restrict__ logits,
           const int*   __restrict__ tags,
           const int*   __restrict__ mask,
           const float* __restrict__ transitions,
           float*       __restrict__ out)
{
    __shared__ __align__(16) unsigned short a_sh[2][K_TAGS];   // fp16, pre-scaled 1/256
    __shared__ float  n0[T_SEQ / 2 + 2];     // normalizer ring (f32, unscaled)
    __shared__ float2 red16[16];
    __shared__ float  mask_sh[T_SEQ];
    __shared__ int    tags_sh[T_SEQ];

    const int b    = blockIdx.x & (N_BATCH - 1);
    const int role = blockIdx.x >> 6;        // 0 = forward, 1 = backward
    const int tid  = threadIdx.x;
    const int j    = tid >> 1;               // column / row
    const int h    = tid & 1;                // half of contraction
    const unsigned base_bt = (unsigned)b * T_SEQ * K_TAGS;

    // ---- stage mask + tags (one element per thread) ----
    {
        int t = tid;
        mask_sh[t] = (float)mask[b * T_SEQ + t];
        tags_sh[t] = tags[b * T_SEQ + t];
    }

    // ---- P half-block into registers: 64 f16x2 ----
    const unsigned* psrc = (role == 0) ? g_Pcol : g_Prow;
    unsigned preg[64];
    #pragma unroll
    for (int m = 0; m < 64; m++) preg[m] = psrc[j * 128 + h * 64 + m];

    if (role == 0) {
        // ================= FORWARD: alpha_0 .. alpha_255 =================
        const float L00 = logits[base_bt];
        float aval = __expf(logits[base_bt + j] - L00);
        if (h == 0) a_sh[0][j] = f2hu(aval * ASCALE);
        if (tid == 0) n0[0] = aval;          // = 1.0
        __syncthreads();

        float lg_cur = logits[base_bt + K_TAGS + j];   // t=1
        #pragma unroll 2
        for (int t = 1; t <= MID; t++) {
            const int rb = (t - 1) & 1, wb = t & 1;
            const float mval = mask_sh[t];
            const int tn = (t < MID) ? t + 1 : MID;
            const float lg_next = logits[base_bt + (unsigned)tn * K_TAGS + j];

            const float eL = __expf(lg_cur);
            const float s  = eL * (ASCALE_R / n0[t - 1]);   // eL * inv0 * 256

            float part = dot128(a_sh[rb] + h * 128, preg);
            float tot  = part + __shfl_xor_sync(0xffffffffu, part, 1);

            const float g = (mval != 0.f) ? tot * s : aval;
            aval = g;
            if (h == 0) a_sh[wb][j] = f2hu(g * ASCALE);
            if (tid == 0) n0[t] = g;           // ring write; no logf on chain
            lg_cur = lg_next;
            __syncthreads();
        }

        // ---- parallel D: D = L00 + sum_{t=1..255} mask_t * log(n0[t-1]) ----
        {
            float dl = 0.f;
            if (tid == 0)        dl = L00;
            else if (tid <= MID) dl = mask_sh[tid] * __logf(n0[tid - 1]);
            #pragma unroll
            for (int o = 16; o; o >>= 1) dl += __shfl_xor_sync(0xffffffffu, dl, o);
            if ((tid & 31) == 0) red16[tid >> 5].x = dl;
            __syncthreads();

            if (h == 0) g_af[b * K_TAGS + j] = aval;
            if (tid == 0) {
                float D = 0.f;
                #pragma unroll
                for (int w = 0; w < 16; w++) D += red16[w].x;
                g_Df[b] = D;
            }
            __syncthreads();
            __threadfence();
            if (tid == 0) atomicExch(&g_flag[b], 1);
        }
    } else {
        // ================= BACKWARD: beta_511 -> beta_255 =================
        float bval = 1.0f;
        if (tid == 0) n0[0] = 1.0f;

        float lg_cur = logits[base_bt + (unsigned)(T_SEQ - 1) * K_TAGS + j];
        __syncthreads();

        #pragma unroll 2
        for (int k = 0; k < 256; k++) {
            const int t  = (T_SEQ - 1) - k;
            const int cb = k & 1;
            const float mval = mask_sh[t];
            const int tn = (t > MID + 1) ? t - 1 : MID + 1;
            const float lg_next = logits[base_bt + (unsigned)tn * K_TAGS + j];

            const float eL = __expf(lg_cur);
            if (h == 0) a_sh[cb][j] = f2hu(eL * bval * ASCALE);   // c = eL ⊙ beta
            __syncthreads();

            const float s = ASCALE_R / n0[k];    // inv0 * 256

            float part = dot128(a_sh[cb] + h * 128, preg);
            float tot  = part + __shfl_xor_sync(0xffffffffu, part, 1);

            const float g = (mval != 0.f) ? tot * s : bval;
            bval = g;
            if (tid == 0) n0[k + 1] = g;
            lg_cur = lg_next;
        }
        __syncthreads();                       // n0 ring complete

        // ---- parallel D_b ----
        float dl = 0.f;
        if (tid < 256) dl = mask_sh[(T_SEQ - 1) - tid] * __logf(n0[tid]);
        #pragma unroll
        for (int o = 16; o; o >>= 1) dl += __shfl_xor_sync(0xffffffffu, dl, o);
        if ((tid & 31) == 0) red16[tid >> 5].y = dl;
        __syncthreads();

        // ---- joint likelihood (moved here: overlaps fwd's chain tail) ----
        float jtot = 0.f;
        {
            int   t  = tid;
            float mt = mask_sh[t];
            int   tg = tags_sh[t];
            float jloc = 0.f;
            if (t < T_SEQ - 1)
                jloc += logits[base_bt + (unsigned)t * K_TAGS + tg] * mt;
            if (t >= 1)
                jloc += transitions[tags_sh[t - 1] * K_TAGS + tg] * mt;
            float msloc = mt;
            #pragma unroll
            for (int o = 16; o; o >>= 1) {
                jloc  += __shfl_xor_sync(0xffffffffu, jloc,  o);
                msloc += __shfl_xor_sync(0xffffffffu, msloc, o);
            }
            if ((tid & 31) == 0) red16[tid >> 5].x = jloc;
            __shared__ float msw[16];
            if ((tid & 31) == 0) msw[tid >> 5] = msloc;
            __syncthreads();
            if (tid == 0) {
                float js = 0.f, ms = 0.f;
                #pragma unroll
                for (int w = 0; w < 16; w++) { js += red16[w].x; ms += msw[w]; }
                int last_idx = (int)ms - 1;
                if (last_idx < 0) last_idx = 0;
                if (last_idx > T_SEQ - 1) last_idx = T_SEQ - 1;
                int ltag = tags_sh[last_idx];
                js += logits[base_bt + (unsigned)(T_SEQ - 1) * K_TAGS + ltag] * mask_sh[T_SEQ - 1];
                red16[0].x = js;               // stash joint
            }
        }

        // ---- wait for forward, combine ----
        if (tid == 0) {
            while (atomicAdd(&g_flag[b], 0) == 0) { }
            __threadfence();
        }
        __syncthreads();
        jtot = red16[0].x;

        float e = (h == 0) ? g_af[b * K_TAGS + j] * bval : 0.f;
        #pragma unroll
        for (int o = 16; o; o >>= 1) e += __shfl_xor_sync(0xffffffffu, e, o);
        __syncthreads();                       // red16.x free for reuse
        if ((tid & 31) == 0) red16[tid >> 5].x = e;
        __syncthreads();
        if (tid == 0) {
            float ssum = 0.f, Db = 0.f;
            #pragma unroll
            for (int w = 0; w < 16; w++) { ssum += red16[w].x; Db += red16[w].y; }
            float log_den = __logf(ssum) + g_Df[b] + Db;
            g_partial[b] = jtot - log_den;
            g_flag[b] = 0;
            __threadfence();
            int n = atomicAdd(&g_done, 1);
            if (n == N_BATCH - 1) {
                __threadfence();
                float acc = 0.f;
                #pragma unroll
                for (int bb = 0; bb < N_BATCH; bb++) acc += g_partial[bb];
                out[0] = acc;
                g_done = 0;
            }
        }
    }
}

extern "C" void kernel_launch(void* const* d_in, const int* in_sizes, int n_in,
                              void* d_out, int out_size)
{
    (void)in_sizes; (void)n_in; (void)out_size;
    const float* logits      = (const float*)d_in[0];
    const int*   tags        = (const int*)  d_in[1];
    const int*   mask        = (const int*)  d_in[2];
    const float* transitions = (const float*)d_in[3];

    pexp_kernel<<<K_TAGS, K_TAGS / 2>>>(transitions);
    crf_kernel<<<2 * N_BATCH, NTHR>>>(logits, tags, mask, transitions, (float*)d_out);
}